// round 14
// baseline (speedup 1.0000x reference)
#include <cuda_runtime.h>
#include <math.h>
#include <stdint.h>

#define SQ   256
#define BBV  64
#define DIN  300
#define HHV  256
#define G4   1024
#define TT   34

typedef unsigned long long ull;

// ---------------- scratch ----------------
__device__ float g_xg_f[SQ * BBV * G4];     // [s][b][col]
__device__ float g_xg_b[SQ * BBV * G4];
__device__ float g_h_f [SQ * HHV * BBV];    // [s][u][b]
__device__ float g_h_b [SQ * HHV * BBV];
__device__ float g_emit[BBV * SQ * TT];     // [b][s][t]
__device__ float g_llh [BBV];
__device__ float g_dummy[32];

// ---------------- f32x2 / cluster helpers ----------------
__device__ __forceinline__ ull fma2(ull a, ull b, ull c) {
    ull d; asm("fma.rn.f32x2 %0, %1, %2, %3;" : "=l"(d) : "l"(a), "l"(b), "l"(c)); return d;
}
__device__ __forceinline__ ull add2(ull a, ull b) {
    ull d; asm("add.rn.f32x2 %0, %1, %2;" : "=l"(d) : "l"(a), "l"(b)); return d;
}
__device__ __forceinline__ ull pack2(float lo, float hi) {
    ull r; asm("mov.b64 %0, {%1, %2};" : "=l"(r) : "f"(lo), "f"(hi)); return r;
}
__device__ __forceinline__ float2 unpack2(ull v) {
    float2 r; asm("mov.b64 {%0, %1}, %2;" : "=f"(r.x), "=f"(r.y) : "l"(v)); return r;
}
__device__ __forceinline__ unsigned smem_u32(const void* p) {
    unsigned a;
    asm("{ .reg .u64 t; cvta.to.shared.u64 t, %1; cvt.u32.u64 %0, t; }" : "=r"(a) : "l"(p));
    return a;
}
__device__ __forceinline__ unsigned mapa_u32(unsigned a, unsigned r) {
    unsigned d; asm("mapa.shared::cluster.u32 %0, %1, %2;" : "=r"(d) : "r"(a), "r"(r)); return d;
}
__device__ __forceinline__ void st_cluster_f128(unsigned a, float4 v) {
    asm volatile("st.shared::cluster.v4.f32 [%0], {%1, %2, %3, %4};"
                 :: "r"(a), "f"(v.x), "f"(v.y), "f"(v.z), "f"(v.w) : "memory");
}
#define CLUSTER_ARRIVE() asm volatile("barrier.cluster.arrive.aligned;" ::: "memory")
#define CLUSTER_WAIT()   asm volatile("barrier.cluster.wait.aligned;"   ::: "memory")

__device__ __forceinline__ float fsigmoid(float x) {
    return __fdividef(1.f, 1.f + __expf(-x));
}
__device__ __forceinline__ float ftanh(float x) {
    float e = __expf(2.f * x);
    return __fdividef(e - 1.f, e + 1.f);
}

// ============================================================================
// Kernel 1: embedding-gather + input projection SGEMM (R9/R10 version, 591us).
// ============================================================================
__global__ void __launch_bounds__(256) input_gemm(
    const float* __restrict__ emb, const int* __restrict__ batch,
    const float* __restrict__ wf, const float* __restrict__ bf,
    const float* __restrict__ wb, const float* __restrict__ bb)
{
    __shared__ __align__(16) float As[8 * 128];
    __shared__ __align__(16) float Bs[8 * 128];

    int tid = threadIdx.x;
    int bm  = blockIdx.y * 128;
    int bnG = blockIdx.x * 128;
    int dir = (bnG >= G4) ? 1 : 0;
    int j0  = bnG - dir * G4;
    const float* W    = dir ? wb : wf;
    const float* bias = dir ? bb : bf;
    float*       outp = dir ? g_xg_b : g_xg_f;

    int am = tid & 127;
    int ak = (tid >> 7) << 2;
    int mg = bm + am;
    int token = batch[(mg & 63) * SQ + (mg >> 6)];
    const float* arow = emb + (size_t)token * DIN;
    const float* wrow = W + (size_t)(j0 + am) * DIN;

    int tx = tid & 15, ty = tid >> 4;
    ull acc2[4][8];
#pragma unroll
    for (int i = 0; i < 4; ++i)
#pragma unroll
        for (int j = 0; j < 8; ++j) acc2[i][j] = 0ULL;

    for (int kk = 0; kk < DIN; kk += 8) {
        int k0 = kk + ak;
        float4 av, bv;
        if (k0 + 3 < DIN) {
            av = *(const float4*)(arow + k0);
            bv = *(const float4*)(wrow + k0);
        } else {
            av = make_float4(k0 < DIN ? arow[k0] : 0.f,
                             k0 + 1 < DIN ? arow[k0 + 1] : 0.f,
                             k0 + 2 < DIN ? arow[k0 + 2] : 0.f, 0.f);
            bv = make_float4(k0 < DIN ? wrow[k0] : 0.f,
                             k0 + 1 < DIN ? wrow[k0 + 1] : 0.f,
                             k0 + 2 < DIN ? wrow[k0 + 2] : 0.f, 0.f);
        }
        As[(ak + 0) * 128 + am] = av.x;
        As[(ak + 1) * 128 + am] = av.y;
        As[(ak + 2) * 128 + am] = av.z;
        As[(ak + 3) * 128 + am] = av.w;
        Bs[(ak + 0) * 128 + am] = bv.x;
        Bs[(ak + 1) * 128 + am] = bv.y;
        Bs[(ak + 2) * 128 + am] = bv.z;
        Bs[(ak + 3) * 128 + am] = bv.w;
        __syncthreads();
#pragma unroll
        for (int k = 0; k < 8; ++k) {
            const ulonglong2* ap = (const ulonglong2*)(As + k * 128 + ty * 8);
            ulonglong2 aA = ap[0], aB = ap[1];
            ull a[4] = {aA.x, aA.y, aB.x, aB.y};
            const float4* bp = (const float4*)(Bs + k * 128 + tx * 8);
            float4 b0 = bp[0], b1 = bp[1];
            ull bd[8];
            bd[0] = pack2(b0.x, b0.x); bd[1] = pack2(b0.y, b0.y);
            bd[2] = pack2(b0.z, b0.z); bd[3] = pack2(b0.w, b0.w);
            bd[4] = pack2(b1.x, b1.x); bd[5] = pack2(b1.y, b1.y);
            bd[6] = pack2(b1.z, b1.z); bd[7] = pack2(b1.w, b1.w);
#pragma unroll
            for (int i = 0; i < 4; ++i)
#pragma unroll
                for (int j = 0; j < 8; ++j)
                    acc2[i][j] = fma2(a[i], bd[j], acc2[i][j]);
        }
        __syncthreads();
    }

    float bb8[8];
#pragma unroll
    for (int j = 0; j < 8; ++j) bb8[j] = bias[j0 + tx * 8 + j];
#pragma unroll
    for (int i2 = 0; i2 < 4; ++i2) {
        int m0 = bm + ty * 8 + 2 * i2;
        float* orow0 = outp + (size_t)m0 * G4 + j0 + tx * 8;
        float* orow1 = orow0 + G4;
#pragma unroll
        for (int j = 0; j < 8; ++j) {
            float2 p = unpack2(acc2[i2][j]);
            orow0[j] = p.x + bb8[j];
            orow1[j] = p.y + bb8[j];
        }
    }
}

// ============================================================================
__global__ void dummy_kernel(int v)
{
    g_dummy[threadIdx.x] = (float)v;
}

// ============================================================================
// Kernel 2: BiLSTM, 8-CTA clusters. MEASUREMENT VARIANT of the R12 kernel:
// the mma phase runs TWICE per step; the duplicate result is stored to a
// dummy smem slot (overwritten before any real read) so ptxas keeps it.
// dur_R14 - dur_R12 ~= 256 * t_mma_phase  ==> splits mma vs exchange cost.
// ============================================================================
__global__ void __cluster_dims__(8, 1, 1) __launch_bounds__(256, 1) lstm_kernel(
    const float* __restrict__ whhf, const float* __restrict__ whhb)
{
    extern __shared__ __align__(16) float sm[];
    float* ws   = sm;                 // [256 k][128 lc]   131072 B
    float* hs   = sm + 32768;         // [2][256 k][8 b]    16384 B
    float* gbuf = sm + 36864;         // [8 b][132]          4224 B
    float* rbuf = gbuf + 1056;        // [128][8]            4096 B
    float* hloc = rbuf + 1024;        // [32 u][8 b]         1024 B

    int tid = threadIdx.x;
    int cid = blockIdx.x >> 3;
    int r   = blockIdx.x & 7;
    int dir = cid >> 3;
    int B0  = (cid & 7) * 8;
    const float* Whh = dir ? whhb : whhf;
    const float* xg  = dir ? g_xg_b : g_xg_f;
    float*       hh  = dir ? g_h_b  : g_h_f;

    for (int idx = tid; idx < 32768; idx += 256) {
        int lc = idx >> 8, k = idx & 255;
        int gcol = ((lc >> 5) << 8) + r * 32 + (lc & 31);
        ws[k * 128 + lc] = Whh[(size_t)gcol * 256 + k];
    }
    for (int i = tid; i < 512; i += 256)
        ((float4*)hs)[i] = make_float4(0.f, 0.f, 0.f, 0.f);
    __syncthreads();

    int ks = tid >> 7, r7 = tid & 127, bp = r7 & 3, cg = r7 >> 2;
    int lc = cg << 2;
    int gcol = ((lc >> 5) << 8) + r * 32 + (lc & 31);
    int cb = tid & 7, cu = tid >> 3;
    int lane = tid & 31, wid = tid >> 5;
    float creg = 0.f;

    unsigned hsa = smem_u32(hs);
    unsigned peer_base = mapa_u32(hsa, (unsigned)wid) + (unsigned)(r * 1024);

    const ulonglong2* wq  = (const ulonglong2*)(ws + ks * 16384 + lc);
    const float2*     hq0 = (const float2*)(hs + ks * 1024 + 2 * bp);

    // prefetch xg for it = 0
    float4 xv0, xv1;
    {
        int s0_ = dir ? 255 : 0;
        const float* xb = xg + ((size_t)(s0_ * 64 + B0 + 2 * bp)) * G4 + gcol;
        if (ks == 0) { xv0 = *(const float4*)xb; xv1 = *(const float4*)(xb + G4); }
    }

    for (int it = 0; it < 256; ++it) {
        int s = dir ? (255 - it) : it;
        int buf = it & 1, nbuf = buf ^ 1;

        ull a00 = 0, a01 = 0, a10 = 0, a11 = 0;
        const float2* hq = hq0 + buf * 1024;

        // ---- mma PASS 1 (real): register double-buffered, 16 chunks of 8 k --
        {
            ulonglong2 wbuf[8]; float2 hbuf[8];
#pragma unroll
            for (int j = 0; j < 8; ++j) { wbuf[j] = wq[j * 32]; hbuf[j] = hq[j * 4]; }
            for (int c = 0; c < 16; ++c) {
                ulonglong2 wn[8]; float2 hn[8];
                if (c < 15) {
                    int base = (c + 1) * 8;
#pragma unroll
                    for (int j = 0; j < 8; ++j) {
                        wn[j] = wq[(base + j) * 32];
                        hn[j] = hq[(base + j) * 4];
                    }
                }
#pragma unroll
                for (int j = 0; j < 8; ++j) {
                    ull hd0 = pack2(hbuf[j].x, hbuf[j].x);
                    ull hd1 = pack2(hbuf[j].y, hbuf[j].y);
                    a00 = fma2(wbuf[j].x, hd0, a00);
                    a01 = fma2(wbuf[j].y, hd0, a01);
                    a10 = fma2(wbuf[j].x, hd1, a10);
                    a11 = fma2(wbuf[j].y, hd1, a11);
                }
#pragma unroll
                for (int j = 0; j < 8; ++j) { wbuf[j] = wn[j]; hbuf[j] = hn[j]; }
            }
        }

        // ---- mma PASS 2 (DUMMY, timing ablation): identical work ----
        ull b00 = 0, b01 = 0, b10 = 0, b11 = 0;
        {
            ulonglong2 wbuf[8]; float2 hbuf[8];
#pragma unroll
            for (int j = 0; j < 8; ++j) { wbuf[j] = wq[j * 32]; hbuf[j] = hq[j * 4]; }
            for (int c = 0; c < 16; ++c) {
                ulonglong2 wn[8]; float2 hn[8];
                if (c < 15) {
                    int base = (c + 1) * 8;
#pragma unroll
                    for (int j = 0; j < 8; ++j) {
                        wn[j] = wq[(base + j) * 32];
                        hn[j] = hq[(base + j) * 4];
                    }
                }
#pragma unroll
                for (int j = 0; j < 8; ++j) {
                    ull hd0 = pack2(hbuf[j].x, hbuf[j].x);
                    ull hd1 = pack2(hbuf[j].y, hbuf[j].y);
                    b00 = fma2(wbuf[j].x, hd0, b00);
                    b01 = fma2(wbuf[j].y, hd0, b01);
                    b10 = fma2(wbuf[j].x, hd1, b10);
                    b11 = fma2(wbuf[j].y, hd1, b11);
                }
#pragma unroll
                for (int j = 0; j < 8; ++j) { wbuf[j] = wn[j]; hbuf[j] = hn[j]; }
            }
        }
        // keep-alive store of dummy accs (racy garbage, overwritten below,
        // never read before the real write)
        {
            ulonglong2* dp = (ulonglong2*)(rbuf + r7 * 8);
            ulonglong2 v0; v0.x = b00; v0.y = b01;
            ulonglong2 v1; v1.x = b10; v1.y = b11;
            dp[0] = v0; dp[1] = v1;
        }
        __syncthreads();

        if (ks == 1) {
            ulonglong2* rp = (ulonglong2*)(rbuf + r7 * 8);
            ulonglong2 v0; v0.x = a00; v0.y = a01;
            ulonglong2 v1; v1.x = a10; v1.y = a11;
            rp[0] = v0; rp[1] = v1;
        }
        __syncthreads();
        if (ks == 0) {
            const ulonglong2* rp = (const ulonglong2*)(rbuf + r7 * 8);
            ulonglong2 p0 = rp[0], p1 = rp[1];
            a00 = add2(a00, p0.x); a01 = add2(a01, p0.y);
            a10 = add2(a10, p1.x); a11 = add2(a11, p1.y);
            float2 c01 = unpack2(a00), c23 = unpack2(a01);
            float2 d01 = unpack2(a10), d23 = unpack2(a11);
            float* q0 = gbuf + (2 * bp) * 132 + lc;
            float* q1 = gbuf + (2 * bp + 1) * 132 + lc;
            q0[0] = c01.x + xv0.x; q0[1] = c01.y + xv0.y;
            q0[2] = c23.x + xv0.z; q0[3] = c23.y + xv0.w;
            q1[0] = d01.x + xv1.x; q1[1] = d01.y + xv1.y;
            q1[2] = d23.x + xv1.z; q1[3] = d23.y + xv1.w;
        }
        __syncthreads();

        // gate combine (torch order i,f,g,o): thread = (unit cu, batch cb)
        float hv;
        {
            float iv = gbuf[cb * 132 +      cu];
            float fv = gbuf[cb * 132 + 32 + cu];
            float gv = gbuf[cb * 132 + 64 + cu];
            float ov = gbuf[cb * 132 + 96 + cu];
            float si = fsigmoid(iv);
            float sf = fsigmoid(fv);
            float so = fsigmoid(ov);
            creg = sf * creg + si * ftanh(gv);
            hv = so * ftanh(creg);
        }

        if (it != 255) {
            hloc[cu * 8 + cb] = hv;
            __syncthreads();
            const float4* srcv = (const float4*)hloc;
            unsigned dstb = peer_base + (unsigned)(nbuf * 8192);
            float4 v0 = srcv[lane];
            float4 v1 = srcv[lane + 32];
            st_cluster_f128(dstb + (unsigned)lane * 16u, v0);
            st_cluster_f128(dstb + (unsigned)(lane + 32) * 16u, v1);
            CLUSTER_ARRIVE();

            hh[(size_t)s * 16384 + (r * 32 + cu) * 64 + B0 + cb] = hv;

            int sn = dir ? (s - 1) : (s + 1);
            if (ks == 0) {
                const float* xb = xg + ((size_t)(sn * 64 + B0 + 2 * bp)) * G4 + gcol;
                xv0 = *(const float4*)xb;
                xv1 = *(const float4*)(xb + G4);
            }
            CLUSTER_WAIT();
        } else {
            hh[(size_t)s * 16384 + (r * 32 + cu) * 64 + B0 + cb] = hv;
        }
    }
}

// ============================================================================
// Kernel 3: emissions (unchanged).
// ============================================================================
__global__ void __launch_bounds__(256) emis_kernel(
    const float* __restrict__ w_out, const float* __restrict__ b_out)
{
    extern __shared__ __align__(16) float hsm[];
    int s = blockIdx.x >> 1, half = blockIdx.x & 1;
    int tid = threadIdx.x;

    const float4* hf = (const float4*)(g_h_f + (size_t)s * 16384) + half * 8;
    const float4* hb = (const float4*)(g_h_b + (size_t)s * 16384) + half * 8;
    for (int f = tid; f < 2048; f += 256) {
        int u = f >> 3, q = f & 7;
        ((float4*)hsm)[u * 8 + q]        = hf[u * 16 + q];
        ((float4*)hsm)[2048 + u * 8 + q] = hb[u * 16 + q];
    }
    __syncthreads();

    for (int o = tid; o < TT * 32; o += 256) {
        int t = o >> 5, b = o & 31;
        const float4* wr = (const float4*)(w_out + (size_t)t * 512);
        float acc = 0.f;
#pragma unroll 4
        for (int u4 = 0; u4 < 128; ++u4) {
            float4 w = __ldg(wr + u4);
            acc += hsm[(u4 * 4 + 0) * 32 + b] * w.x
                 + hsm[(u4 * 4 + 1) * 32 + b] * w.y
                 + hsm[(u4 * 4 + 2) * 32 + b] * w.z
                 + hsm[(u4 * 4 + 3) * 32 + b] * w.w;
        }
        g_emit[((size_t)(half * 32 + b) * SQ + s) * TT + t] = acc + __ldg(b_out + t);
    }
}

// ============================================================================
// Kernel 4: CRF NLL (unchanged).
// ============================================================================
__global__ void __launch_bounds__(64) crf_kernel(
    const int* __restrict__ tags,
    const float* __restrict__ start_t, const float* __restrict__ end_t,
    const float* __restrict__ trans)
{
    __shared__ float bufA[40], bufB[40];
    __shared__ float red[64];
    int b = blockIdx.x, tid = threadIdx.x;
    const float* em = g_emit + (size_t)b * SQ * TT;

    float trw[TT];
    float emv_nxt = 0.f;
    if (tid < TT) {
#pragma unroll
        for (int t = 0; t < TT; ++t) trw[t] = __ldg(&trans[t * TT + tid]);
        bufA[tid] = start_t[tid] + em[tid];
        emv_nxt = em[TT + tid];
    }
    __syncthreads();

    float* cur = bufA;
    float* nxt = bufB;
    for (int s = 1; s < SQ; ++s) {
        if (tid < TT) {
            float emv = emv_nxt;
            if (s + 1 < SQ) emv_nxt = em[(s + 1) * TT + tid];
            float C = cur[0];
            float s0 = 0.f, s1 = 0.f, s2 = 0.f, s3 = 0.f;
#pragma unroll
            for (int i = 0; i < 8; ++i) {
                s0 += __expf(cur[4 * i + 0] + trw[4 * i + 0] - C);
                s1 += __expf(cur[4 * i + 1] + trw[4 * i + 1] - C);
                s2 += __expf(cur[4 * i + 2] + trw[4 * i + 2] - C);
                s3 += __expf(cur[4 * i + 3] + trw[4 * i + 3] - C);
            }
            s0 += __expf(cur[32] + trw[32] - C);
            s1 += __expf(cur[33] + trw[33] - C);
            nxt[tid] = C + __logf((s0 + s1) + (s2 + s3)) + emv;
        }
        __syncthreads();
        float* t_ = cur; cur = nxt; nxt = t_;
    }

    const int* tb = tags + b * SQ;
    float np = 0.f;
    for (int s = tid; s < SQ; s += 64)     np += em[s * TT + tb[s]];
    for (int s = tid; s < SQ - 1; s += 64) np += __ldg(&trans[tb[s] * TT + tb[s + 1]]);
    red[tid] = np;
    __syncthreads();
    if (tid < 32) {
        float a = red[tid] + red[tid + 32];
#pragma unroll
        for (int o = 16; o > 0; o >>= 1) a += __shfl_xor_sync(0xffffffffu, a, o);
        if (tid == 0) {
            float C = cur[0];
            float sum = 0.f;
            for (int q = 0; q < TT; ++q) sum += __expf(cur[q] + end_t[q] - C);
            float den = C + __logf(sum);
            float num = a + start_t[tb[0]] + end_t[tb[SQ - 1]];
            g_llh[b] = num - den;
        }
    }
}

// ============================================================================
__global__ void __launch_bounds__(64) finalize_kernel(float* out)
{
    __shared__ float r[64];
    int t = threadIdx.x;
    r[t] = g_llh[t];
    __syncthreads();
    for (int o = 32; o > 0; o >>= 1) {
        if (t < o) r[t] += r[t + o];
        __syncthreads();
    }
    if (t == 0) out[0] = -r[0] / 64.f;
}

// ============================================================================
// MEASUREMENT ROUND: doubled-mma LSTM isolates t_mma vs exchange:
//   dur - 2414 ~= 256 * t_mma_phase
// Decision: delta < 700us -> exchange is the elephant (R15: mbarrier
// point-to-point + cross-step pipelining). delta >= 1000us -> mma is the
// elephant (R15: tcgen05 bf16x3 recurrence).
// ============================================================================
extern "C" void kernel_launch(void* const* d_in, const int* in_sizes, int n_in,
                              void* d_out, int out_size)
{
    const int*   batch   = (const int*)  d_in[0];
    const int*   tags    = (const int*)  d_in[1];
    const float* emb     = (const float*)d_in[3];
    const float* w_ih_f  = (const float*)d_in[4];
    const float* w_hh_f  = (const float*)d_in[5];
    const float* b_f     = (const float*)d_in[6];
    const float* w_ih_b  = (const float*)d_in[7];
    const float* w_hh_b  = (const float*)d_in[8];
    const float* b_b     = (const float*)d_in[9];
    const float* w_out   = (const float*)d_in[10];
    const float* b_out   = (const float*)d_in[11];
    const float* start_t = (const float*)d_in[12];
    const float* end_t   = (const float*)d_in[13];
    const float* trans   = (const float*)d_in[14];
    float* out = (float*)d_out;

    const int LSTM_SMEM = (32768 + 4096 + 1056 + 1024 + 256) * 4;  // 156800 B
    const int EMIS_SMEM = 512 * 32 * 4;                            // 65536 B
    cudaFuncSetAttribute(lstm_kernel, cudaFuncAttributeMaxDynamicSharedMemorySize, LSTM_SMEM);
    cudaFuncSetAttribute(emis_kernel, cudaFuncAttributeMaxDynamicSharedMemorySize, EMIS_SMEM);

    input_gemm<<<dim3(16, 128), 256>>>(emb, batch, w_ih_f, b_f, w_ih_b, b_b);  // slot 1
    dummy_kernel<<<1, 32>>>(1);                                                // slot 2
    dummy_kernel<<<1, 32>>>(2);                                                // slot 3
    lstm_kernel<<<128, 256, LSTM_SMEM>>>(w_hh_f, w_hh_b);                      // slot 4 <- profiled
    emis_kernel<<<512, 256, EMIS_SMEM>>>(w_out, b_out);                        // slot 5
    crf_kernel<<<64, 64>>>(tags, start_t, end_t, trans);                       // slot 6
    finalize_kernel<<<1, 64>>>(out);                                           // slot 7
}

// round 15
// speedup vs baseline: 1.1455x; 1.1455x over previous
#include <cuda_runtime.h>
#include <math.h>
#include <stdint.h>

#define SQ   256
#define BBV  64
#define DIN  300
#define HHV  256
#define G4   1024
#define TT   34

typedef unsigned long long ull;

// ---------------- scratch ----------------
__device__ float g_xg_f[SQ * BBV * G4];     // [s][b][col'], col' = u*4+gate
__device__ float g_xg_b[SQ * BBV * G4];
__device__ float g_h_f [SQ * HHV * BBV];    // [s][u][b]
__device__ float g_h_b [SQ * HHV * BBV];
__device__ float g_emit[BBV * SQ * TT];     // [b][s][t]
__device__ float g_llh [BBV];
__device__ float g_dummy[32];

// ---------------- f32x2 / cluster helpers ----------------
__device__ __forceinline__ ull fma2(ull a, ull b, ull c) {
    ull d; asm("fma.rn.f32x2 %0, %1, %2, %3;" : "=l"(d) : "l"(a), "l"(b), "l"(c)); return d;
}
__device__ __forceinline__ ull add2(ull a, ull b) {
    ull d; asm("add.rn.f32x2 %0, %1, %2;" : "=l"(d) : "l"(a), "l"(b)); return d;
}
__device__ __forceinline__ ull pack2(float lo, float hi) {
    ull r; asm("mov.b64 %0, {%1, %2};" : "=l"(r) : "f"(lo), "f"(hi)); return r;
}
__device__ __forceinline__ float2 unpack2(ull v) {
    float2 r; asm("mov.b64 {%0, %1}, %2;" : "=f"(r.x), "=f"(r.y) : "l"(v)); return r;
}
__device__ __forceinline__ unsigned smem_u32(const void* p) {
    unsigned a;
    asm("{ .reg .u64 t; cvta.to.shared.u64 t, %1; cvt.u32.u64 %0, t; }" : "=r"(a) : "l"(p));
    return a;
}
__device__ __forceinline__ unsigned mapa_u32(unsigned a, unsigned r) {
    unsigned d; asm("mapa.shared::cluster.u32 %0, %1, %2;" : "=r"(d) : "r"(a), "r"(r)); return d;
}
__device__ __forceinline__ void st_cluster_f128(unsigned a, float4 v) {
    asm volatile("st.shared::cluster.v4.f32 [%0], {%1, %2, %3, %4};"
                 :: "r"(a), "f"(v.x), "f"(v.y), "f"(v.z), "f"(v.w) : "memory");
}
#define CLUSTER_ARRIVE() asm volatile("barrier.cluster.arrive.aligned;" ::: "memory")
#define CLUSTER_WAIT()   asm volatile("barrier.cluster.wait.aligned;"   ::: "memory")

__device__ __forceinline__ float fsigmoid(float x) {
    return __fdividef(1.f, 1.f + __expf(-x));
}
__device__ __forceinline__ float ftanh(float x) {
    float e = __expf(2.f * x);
    return __fdividef(e - 1.f, e + 1.f);
}

// ============================================================================
// Kernel 1: embedding-gather + input projection SGEMM.
// NEW: epilogue writes xg in gate-interleaved layout col' = (col&255)*4 +
// (col>>8), so the LSTM's combine can be fused thread-locally.
// ============================================================================
__global__ void __launch_bounds__(256) input_gemm(
    const float* __restrict__ emb, const int* __restrict__ batch,
    const float* __restrict__ wf, const float* __restrict__ bf,
    const float* __restrict__ wb, const float* __restrict__ bb)
{
    __shared__ __align__(16) float As[8 * 128];
    __shared__ __align__(16) float Bs[8 * 128];

    int tid = threadIdx.x;
    int bm  = blockIdx.y * 128;
    int bnG = blockIdx.x * 128;
    int dir = (bnG >= G4) ? 1 : 0;
    int j0  = bnG - dir * G4;
    const float* W    = dir ? wb : wf;
    const float* bias = dir ? bb : bf;
    float*       outp = dir ? g_xg_b : g_xg_f;

    int am = tid & 127;
    int ak = (tid >> 7) << 2;
    int mg = bm + am;
    int token = batch[(mg & 63) * SQ + (mg >> 6)];
    const float* arow = emb + (size_t)token * DIN;
    const float* wrow = W + (size_t)(j0 + am) * DIN;

    int tx = tid & 15, ty = tid >> 4;
    ull acc2[4][8];
#pragma unroll
    for (int i = 0; i < 4; ++i)
#pragma unroll
        for (int j = 0; j < 8; ++j) acc2[i][j] = 0ULL;

    for (int kk = 0; kk < DIN; kk += 8) {
        int k0 = kk + ak;
        float4 av, bv;
        if (k0 + 3 < DIN) {
            av = *(const float4*)(arow + k0);
            bv = *(const float4*)(wrow + k0);
        } else {
            av = make_float4(k0 < DIN ? arow[k0] : 0.f,
                             k0 + 1 < DIN ? arow[k0 + 1] : 0.f,
                             k0 + 2 < DIN ? arow[k0 + 2] : 0.f, 0.f);
            bv = make_float4(k0 < DIN ? wrow[k0] : 0.f,
                             k0 + 1 < DIN ? wrow[k0 + 1] : 0.f,
                             k0 + 2 < DIN ? wrow[k0 + 2] : 0.f, 0.f);
        }
        As[(ak + 0) * 128 + am] = av.x;
        As[(ak + 1) * 128 + am] = av.y;
        As[(ak + 2) * 128 + am] = av.z;
        As[(ak + 3) * 128 + am] = av.w;
        Bs[(ak + 0) * 128 + am] = bv.x;
        Bs[(ak + 1) * 128 + am] = bv.y;
        Bs[(ak + 2) * 128 + am] = bv.z;
        Bs[(ak + 3) * 128 + am] = bv.w;
        __syncthreads();
#pragma unroll
        for (int k = 0; k < 8; ++k) {
            const ulonglong2* ap = (const ulonglong2*)(As + k * 128 + ty * 8);
            ulonglong2 aA = ap[0], aB = ap[1];
            ull a[4] = {aA.x, aA.y, aB.x, aB.y};
            const float4* bp = (const float4*)(Bs + k * 128 + tx * 8);
            float4 b0 = bp[0], b1 = bp[1];
            ull bd[8];
            bd[0] = pack2(b0.x, b0.x); bd[1] = pack2(b0.y, b0.y);
            bd[2] = pack2(b0.z, b0.z); bd[3] = pack2(b0.w, b0.w);
            bd[4] = pack2(b1.x, b1.x); bd[5] = pack2(b1.y, b1.y);
            bd[6] = pack2(b1.z, b1.z); bd[7] = pack2(b1.w, b1.w);
#pragma unroll
            for (int i = 0; i < 4; ++i)
#pragma unroll
                for (int j = 0; j < 8; ++j)
                    acc2[i][j] = fma2(a[i], bd[j], acc2[i][j]);
        }
        __syncthreads();
    }

    // epilogue: gate-interleaved scatter col' = (col&255)*4 + gate
    int colbase = j0 + tx * 8;
    int gate = colbase >> 8;              // constant within this 128-col tile
    float bb8[8];
#pragma unroll
    for (int j = 0; j < 8; ++j) bb8[j] = bias[colbase + j];
#pragma unroll
    for (int i2 = 0; i2 < 4; ++i2) {
        int m0 = bm + ty * 8 + 2 * i2;
        float* base0 = outp + (size_t)m0 * G4 + ((colbase & 255) << 2) + gate;
        float* base1 = base0 + G4;
#pragma unroll
        for (int j = 0; j < 8; ++j) {
            float2 p = unpack2(acc2[i2][j]);
            base0[j * 4] = p.x + bb8[j];
            base1[j * 4] = p.y + bb8[j];
        }
    }
}

// ============================================================================
__global__ void dummy_kernel(int v)
{
    g_dummy[threadIdx.x] = (float)v;
}

// ============================================================================
// Kernel 2: BiLSTM, 8-CTA clusters. NEW vs R12:
//  - ws gate-interleaved (c = u*4+gate): thread owns 1 unit's 4 gates x 2 b
//  - h stored PRE-DUPLICATED ({h,h} ull) -> no pack2 in inner loop
//  - combine fused into the ks==0 reducer thread (no gbuf, one less sync)
// Inner loop/k: 2x LDS.128 + 4 fma2 (was 2 LDS + 2 pack + 4 fma2).
// ============================================================================
__global__ void __cluster_dims__(8, 1, 1) __launch_bounds__(256, 1) lstm_kernel(
    const float* __restrict__ whhf, const float* __restrict__ whhb)
{
    extern __shared__ __align__(16) float sm[];
    float* ws    = sm;                 // [256 k][128 c] gate-interleaved  131072 B
    float* hsd   = sm + 32768;         // [2][256 k][8 b] ull dup          32768 B
    float* rbuf  = sm + 32768 + 8192;  // [128 tiles][4 ull]                4096 B
    float* hlocd = rbuf + 1024;        // [32 u][8 b] ull dup               2048 B

    int tid = threadIdx.x;
    int cid = blockIdx.x >> 3;
    int r   = blockIdx.x & 7;
    int dir = cid >> 3;
    int B0  = (cid & 7) * 8;
    const float* Whh = dir ? whhb : whhf;
    const float* xg  = dir ? g_xg_b : g_xg_f;
    float*       hh  = dir ? g_h_b  : g_h_f;

    // weights gate-interleaved: ws[k][u*4+g] = Whh[(g*256 + r*32 + u)*256 + k]
    for (int idx = tid; idx < 32768; idx += 256) {
        int c = idx >> 8, k = idx & 255;
        int u = c >> 2, g = c & 3;
        ws[k * 128 + c] = Whh[(size_t)(g * 256 + r * 32 + u) * 256 + k];
    }
    for (int i = tid; i < 1024; i += 256)   // zero hsd buffer 0 (16 KB)
        ((float4*)hsd)[i] = make_float4(0.f, 0.f, 0.f, 0.f);
    __syncthreads();

    int ks = tid >> 7;                 // k half
    int t7 = tid & 127;
    int u  = t7 >> 2;                  // local unit 0..31
    int bp = t7 & 3;                   // batch pair 0..3 (b = 2bp, 2bp+1)
    int lane = tid & 31, wid = tid >> 5;
    float creg0 = 0.f, creg1 = 0.f;

    unsigned hsda = smem_u32(hsd);
    unsigned peer_base = mapa_u32(hsda, (unsigned)wid) + (unsigned)(r * 2048);

    const ulonglong2* wq  = (const ulonglong2*)ws + (ks * 128) * 32 + u;   // +32/k
    const ulonglong2* hq0 = (const ulonglong2*)hsd + (ks * 128) * 4 + bp;  // +4/k

    // prefetch xg (gate-interleaved) for it = 0
    float4 xv0, xv1;
    {
        int s0_ = dir ? 255 : 0;
        const float* xb = xg + ((size_t)(s0_ * 64 + B0 + 2 * bp)) * G4 + (r * 32 + u) * 4;
        if (ks == 0) { xv0 = *(const float4*)xb; xv1 = *(const float4*)(xb + G4); }
    }

    for (int it = 0; it < 256; ++it) {
        int s = dir ? (255 - it) : it;
        int buf = it & 1, nbuf = buf ^ 1;

        // accs: {i,f} b0, {g,o} b0, {i,f} b1, {g,o} b1
        ull aIF0 = 0, aGO0 = 0, aIF1 = 0, aGO1 = 0;
        const ulonglong2* hq = hq0 + buf * 1024;

        // ---- register double-buffered mma: 16 chunks of 8 k ----
        ulonglong2 wb_[8], hb_[8];
#pragma unroll
        for (int j = 0; j < 8; ++j) { wb_[j] = wq[j * 32]; hb_[j] = hq[j * 4]; }
        for (int c = 0; c < 16; ++c) {
            ulonglong2 wn[8], hn[8];
            if (c < 15) {
                int base = (c + 1) * 8;
#pragma unroll
                for (int j = 0; j < 8; ++j) {
                    wn[j] = wq[(base + j) * 32];
                    hn[j] = hq[(base + j) * 4];
                }
            }
#pragma unroll
            for (int j = 0; j < 8; ++j) {
                aIF0 = fma2(wb_[j].x, hb_[j].x, aIF0);
                aGO0 = fma2(wb_[j].y, hb_[j].x, aGO0);
                aIF1 = fma2(wb_[j].x, hb_[j].y, aIF1);
                aGO1 = fma2(wb_[j].y, hb_[j].y, aGO1);
            }
#pragma unroll
            for (int j = 0; j < 8; ++j) { wb_[j] = wn[j]; hb_[j] = hn[j]; }
        }

        if (ks == 1) {
            ulonglong2* rp = (ulonglong2*)rbuf + t7 * 2;
            ulonglong2 v0; v0.x = aIF0; v0.y = aGO0;
            ulonglong2 v1; v1.x = aIF1; v1.y = aGO1;
            rp[0] = v0; rp[1] = v1;
        }
        __syncthreads();

        if (ks == 0) {
            const ulonglong2* rp = (const ulonglong2*)rbuf + t7 * 2;
            ulonglong2 p0 = rp[0], p1 = rp[1];
            aIF0 = add2(aIF0, p0.x); aGO0 = add2(aGO0, p0.y);
            aIF1 = add2(aIF1, p1.x); aGO1 = add2(aGO1, p1.y);

            // fused gate combine (torch order i,f,g,o)
            float2 if0 = unpack2(aIF0), go0 = unpack2(aGO0);
            float2 if1 = unpack2(aIF1), go1 = unpack2(aGO1);
            float i0 = if0.x + xv0.x, f0 = if0.y + xv0.y;
            float g0 = go0.x + xv0.z, o0 = go0.y + xv0.w;
            float i1 = if1.x + xv1.x, f1 = if1.y + xv1.y;
            float g1 = go1.x + xv1.z, o1 = go1.y + xv1.w;
            creg0 = fsigmoid(f0) * creg0 + fsigmoid(i0) * ftanh(g0);
            creg1 = fsigmoid(f1) * creg1 + fsigmoid(i1) * ftanh(g1);
            float h0 = fsigmoid(o0) * ftanh(creg0);
            float h1 = fsigmoid(o1) * ftanh(creg1);

            // h history (for emissions) + duplicated local staging
            *(float2*)&hh[(size_t)s * 16384 + (r * 32 + u) * 64 + B0 + 2 * bp] =
                make_float2(h0, h1);
            ulonglong2 hd; hd.x = pack2(h0, h0); hd.y = pack2(h1, h1);
            ((ulonglong2*)hlocd)[u * 4 + bp] = hd;
        }

        if (it != 255) {
            __syncthreads();
            // warp `wid` copies the dup'd 2KB slice to peer `wid` (4 f4/lane)
            const float4* srcv = (const float4*)hlocd;
            unsigned dstb = peer_base + (unsigned)(nbuf * 16384);
#pragma unroll
            for (int q = 0; q < 4; ++q) {
                float4 v = srcv[lane + 32 * q];
                st_cluster_f128(dstb + (unsigned)(lane + 32 * q) * 16u, v);
            }
            CLUSTER_ARRIVE();

            int sn = dir ? (s - 1) : (s + 1);
            if (ks == 0) {
                const float* xb = xg + ((size_t)(sn * 64 + B0 + 2 * bp)) * G4 + (r * 32 + u) * 4;
                xv0 = *(const float4*)xb;
                xv1 = *(const float4*)(xb + G4);
            }
            CLUSTER_WAIT();
        }
    }
}

// ============================================================================
// Kernel 3: emissions (unchanged; hh layout unchanged).
// ============================================================================
__global__ void __launch_bounds__(256) emis_kernel(
    const float* __restrict__ w_out, const float* __restrict__ b_out)
{
    extern __shared__ __align__(16) float hsm[];
    int s = blockIdx.x >> 1, half = blockIdx.x & 1;
    int tid = threadIdx.x;

    const float4* hf = (const float4*)(g_h_f + (size_t)s * 16384) + half * 8;
    const float4* hb = (const float4*)(g_h_b + (size_t)s * 16384) + half * 8;
    for (int f = tid; f < 2048; f += 256) {
        int u = f >> 3, q = f & 7;
        ((float4*)hsm)[u * 8 + q]        = hf[u * 16 + q];
        ((float4*)hsm)[2048 + u * 8 + q] = hb[u * 16 + q];
    }
    __syncthreads();

    for (int o = tid; o < TT * 32; o += 256) {
        int t = o >> 5, b = o & 31;
        const float4* wr = (const float4*)(w_out + (size_t)t * 512);
        float acc = 0.f;
#pragma unroll 4
        for (int u4 = 0; u4 < 128; ++u4) {
            float4 w = __ldg(wr + u4);
            acc += hsm[(u4 * 4 + 0) * 32 + b] * w.x
                 + hsm[(u4 * 4 + 1) * 32 + b] * w.y
                 + hsm[(u4 * 4 + 2) * 32 + b] * w.z
                 + hsm[(u4 * 4 + 3) * 32 + b] * w.w;
        }
        g_emit[((size_t)(half * 32 + b) * SQ + s) * TT + t] = acc + __ldg(b_out + t);
    }
}

// ============================================================================
// Kernel 4: CRF NLL (unchanged).
// ============================================================================
__global__ void __launch_bounds__(64) crf_kernel(
    const int* __restrict__ tags,
    const float* __restrict__ start_t, const float* __restrict__ end_t,
    const float* __restrict__ trans)
{
    __shared__ float bufA[40], bufB[40];
    __shared__ float red[64];
    int b = blockIdx.x, tid = threadIdx.x;
    const float* em = g_emit + (size_t)b * SQ * TT;

    float trw[TT];
    float emv_nxt = 0.f;
    if (tid < TT) {
#pragma unroll
        for (int t = 0; t < TT; ++t) trw[t] = __ldg(&trans[t * TT + tid]);
        bufA[tid] = start_t[tid] + em[tid];
        emv_nxt = em[TT + tid];
    }
    __syncthreads();

    float* cur = bufA;
    float* nxt = bufB;
    for (int s = 1; s < SQ; ++s) {
        if (tid < TT) {
            float emv = emv_nxt;
            if (s + 1 < SQ) emv_nxt = em[(s + 1) * TT + tid];
            float C = cur[0];
            float s0 = 0.f, s1 = 0.f, s2 = 0.f, s3 = 0.f;
#pragma unroll
            for (int i = 0; i < 8; ++i) {
                s0 += __expf(cur[4 * i + 0] + trw[4 * i + 0] - C);
                s1 += __expf(cur[4 * i + 1] + trw[4 * i + 1] - C);
                s2 += __expf(cur[4 * i + 2] + trw[4 * i + 2] - C);
                s3 += __expf(cur[4 * i + 3] + trw[4 * i + 3] - C);
            }
            s0 += __expf(cur[32] + trw[32] - C);
            s1 += __expf(cur[33] + trw[33] - C);
            nxt[tid] = C + __logf((s0 + s1) + (s2 + s3)) + emv;
        }
        __syncthreads();
        float* t_ = cur; cur = nxt; nxt = t_;
    }

    const int* tb = tags + b * SQ;
    float np = 0.f;
    for (int s = tid; s < SQ; s += 64)     np += em[s * TT + tb[s]];
    for (int s = tid; s < SQ - 1; s += 64) np += __ldg(&trans[tb[s] * TT + tb[s + 1]]);
    red[tid] = np;
    __syncthreads();
    if (tid < 32) {
        float a = red[tid] + red[tid + 32];
#pragma unroll
        for (int o = 16; o > 0; o >>= 1) a += __shfl_xor_sync(0xffffffffu, a, o);
        if (tid == 0) {
            float C = cur[0];
            float sum = 0.f;
            for (int q = 0; q < TT; ++q) sum += __expf(cur[q] + end_t[q] - C);
            float den = C + __logf(sum);
            float num = a + start_t[tb[0]] + end_t[tb[SQ - 1]];
            g_llh[b] = num - den;
        }
    }
}

// ============================================================================
__global__ void __launch_bounds__(64) finalize_kernel(float* out)
{
    __shared__ float r[64];
    int t = threadIdx.x;
    r[t] = g_llh[t];
    __syncthreads();
    for (int o = 32; o > 0; o >>= 1) {
        if (t < o) r[t] += r[t + o];
        __syncthreads();
    }
    if (t == 0) out[0] = -r[0] / 64.f;
}

// ============================================================================
extern "C" void kernel_launch(void* const* d_in, const int* in_sizes, int n_in,
                              void* d_out, int out_size)
{
    const int*   batch   = (const int*)  d_in[0];
    const int*   tags    = (const int*)  d_in[1];
    const float* emb     = (const float*)d_in[3];
    const float* w_ih_f  = (const float*)d_in[4];
    const float* w_hh_f  = (const float*)d_in[5];
    const float* b_f     = (const float*)d_in[6];
    const float* w_ih_b  = (const float*)d_in[7];
    const float* w_hh_b  = (const float*)d_in[8];
    const float* b_b     = (const float*)d_in[9];
    const float* w_out   = (const float*)d_in[10];
    const float* b_out   = (const float*)d_in[11];
    const float* start_t = (const float*)d_in[12];
    const float* end_t   = (const float*)d_in[13];
    const float* trans   = (const float*)d_in[14];
    float* out = (float*)d_out;

    const int LSTM_SMEM = (32768 + 8192 + 1024 + 512) * 4;   // 169984 B
    const int EMIS_SMEM = 512 * 32 * 4;                      // 65536 B
    cudaFuncSetAttribute(lstm_kernel, cudaFuncAttributeMaxDynamicSharedMemorySize, LSTM_SMEM);
    cudaFuncSetAttribute(emis_kernel, cudaFuncAttributeMaxDynamicSharedMemorySize, EMIS_SMEM);

    input_gemm<<<dim3(16, 128), 256>>>(emb, batch, w_ih_f, b_f, w_ih_b, b_b);  // slot 1
    dummy_kernel<<<1, 32>>>(1);                                                // slot 2
    dummy_kernel<<<1, 32>>>(2);                                                // slot 3
    lstm_kernel<<<128, 256, LSTM_SMEM>>>(w_hh_f, w_hh_b);                      // slot 4 <- profiled
    emis_kernel<<<512, 256, EMIS_SMEM>>>(w_out, b_out);                        // slot 5
    crf_kernel<<<64, 64>>>(tags, start_t, end_t, trans);                       // slot 6
    finalize_kernel<<<1, 64>>>(out);                                           // slot 7
}

// round 17
// speedup vs baseline: 1.6459x; 1.4368x over previous
#include <cuda_runtime.h>
#include <math.h>
#include <stdint.h>

#define SQ   256
#define BBV  64
#define DIN  300
#define HHV  256
#define G4   1024
#define TT   34

typedef unsigned long long ull;

// ---------------- scratch ----------------
__device__ float g_xg_f[SQ * BBV * G4];     // [s][b][col'], col' = u*4+gate
__device__ float g_xg_b[SQ * BBV * G4];
__device__ float g_h_f [SQ * HHV * BBV];    // [s][u][b]
__device__ float g_h_b [SQ * HHV * BBV];
__device__ float g_emit[BBV * SQ * TT];     // [b][s][t]
__device__ float g_llh [BBV];
__device__ float g_dummy[32];

// ---------------- f32x2 / cluster helpers ----------------
__device__ __forceinline__ ull fma2(ull a, ull b, ull c) {
    ull d; asm("fma.rn.f32x2 %0, %1, %2, %3;" : "=l"(d) : "l"(a), "l"(b), "l"(c)); return d;
}
__device__ __forceinline__ ull add2(ull a, ull b) {
    ull d; asm("add.rn.f32x2 %0, %1, %2;" : "=l"(d) : "l"(a), "l"(b)); return d;
}
__device__ __forceinline__ ull pack2(float lo, float hi) {
    ull r; asm("mov.b64 %0, {%1, %2};" : "=l"(r) : "f"(lo), "f"(hi)); return r;
}
__device__ __forceinline__ float2 unpack2(ull v) {
    float2 r; asm("mov.b64 {%0, %1}, %2;" : "=f"(r.x), "=f"(r.y) : "l"(v)); return r;
}
__device__ __forceinline__ unsigned smem_u32(const void* p) {
    unsigned a;
    asm("{ .reg .u64 t; cvta.to.shared.u64 t, %1; cvt.u32.u64 %0, t; }" : "=r"(a) : "l"(p));
    return a;
}
__device__ __forceinline__ unsigned mapa_u32(unsigned a, unsigned r) {
    unsigned d; asm("mapa.shared::cluster.u32 %0, %1, %2;" : "=r"(d) : "r"(a), "r"(r)); return d;
}
__device__ __forceinline__ void st_cluster_f32(unsigned a, float v) {
    asm volatile("st.shared::cluster.f32 [%0], %1;" :: "r"(a), "f"(v) : "memory");
}
#define CLUSTER_ARRIVE() asm volatile("barrier.cluster.arrive.aligned;" ::: "memory")
#define CLUSTER_WAIT()   asm volatile("barrier.cluster.wait.aligned;"   ::: "memory")

__device__ __forceinline__ float fsigmoid(float x) {
    return __fdividef(1.f, 1.f + __expf(-x));
}
__device__ __forceinline__ float ftanh(float x) {
    float e = __expf(2.f * x);
    return __fdividef(e - 1.f, e + 1.f);
}

// ============================================================================
// Kernel 1: embedding-gather + input projection SGEMM (gate-interleaved
// epilogue col' = (col&255)*4 + (col>>8)).
// ============================================================================
__global__ void __launch_bounds__(256) input_gemm(
    const float* __restrict__ emb, const int* __restrict__ batch,
    const float* __restrict__ wf, const float* __restrict__ bf,
    const float* __restrict__ wb, const float* __restrict__ bb)
{
    __shared__ __align__(16) float As[8 * 128];
    __shared__ __align__(16) float Bs[8 * 128];

    int tid = threadIdx.x;
    int bm  = blockIdx.y * 128;
    int bnG = blockIdx.x * 128;
    int dir = (bnG >= G4) ? 1 : 0;
    int j0  = bnG - dir * G4;
    const float* W    = dir ? wb : wf;
    const float* bias = dir ? bb : bf;
    float*       outp = dir ? g_xg_b : g_xg_f;

    int am = tid & 127;
    int ak = (tid >> 7) << 2;
    int mg = bm + am;
    int token = batch[(mg & 63) * SQ + (mg >> 6)];
    const float* arow = emb + (size_t)token * DIN;
    const float* wrow = W + (size_t)(j0 + am) * DIN;

    int tx = tid & 15, ty = tid >> 4;
    ull acc2[4][8];
#pragma unroll
    for (int i = 0; i < 4; ++i)
#pragma unroll
        for (int j = 0; j < 8; ++j) acc2[i][j] = 0ULL;

    for (int kk = 0; kk < DIN; kk += 8) {
        int k0 = kk + ak;
        float4 av, bv;
        if (k0 + 3 < DIN) {
            av = *(const float4*)(arow + k0);
            bv = *(const float4*)(wrow + k0);
        } else {
            av = make_float4(k0 < DIN ? arow[k0] : 0.f,
                             k0 + 1 < DIN ? arow[k0 + 1] : 0.f,
                             k0 + 2 < DIN ? arow[k0 + 2] : 0.f, 0.f);
            bv = make_float4(k0 < DIN ? wrow[k0] : 0.f,
                             k0 + 1 < DIN ? wrow[k0 + 1] : 0.f,
                             k0 + 2 < DIN ? wrow[k0 + 2] : 0.f, 0.f);
        }
        As[(ak + 0) * 128 + am] = av.x;
        As[(ak + 1) * 128 + am] = av.y;
        As[(ak + 2) * 128 + am] = av.z;
        As[(ak + 3) * 128 + am] = av.w;
        Bs[(ak + 0) * 128 + am] = bv.x;
        Bs[(ak + 1) * 128 + am] = bv.y;
        Bs[(ak + 2) * 128 + am] = bv.z;
        Bs[(ak + 3) * 128 + am] = bv.w;
        __syncthreads();
#pragma unroll
        for (int k = 0; k < 8; ++k) {
            const ulonglong2* ap = (const ulonglong2*)(As + k * 128 + ty * 8);
            ulonglong2 aA = ap[0], aB = ap[1];
            ull a[4] = {aA.x, aA.y, aB.x, aB.y};
            const float4* bp = (const float4*)(Bs + k * 128 + tx * 8);
            float4 b0 = bp[0], b1 = bp[1];
            ull bd[8];
            bd[0] = pack2(b0.x, b0.x); bd[1] = pack2(b0.y, b0.y);
            bd[2] = pack2(b0.z, b0.z); bd[3] = pack2(b0.w, b0.w);
            bd[4] = pack2(b1.x, b1.x); bd[5] = pack2(b1.y, b1.y);
            bd[6] = pack2(b1.z, b1.z); bd[7] = pack2(b1.w, b1.w);
#pragma unroll
            for (int i = 0; i < 4; ++i)
#pragma unroll
                for (int j = 0; j < 8; ++j)
                    acc2[i][j] = fma2(a[i], bd[j], acc2[i][j]);
        }
        __syncthreads();
    }

    int colbase = j0 + tx * 8;
    int gate = colbase >> 8;
    float bb8[8];
#pragma unroll
    for (int j = 0; j < 8; ++j) bb8[j] = bias[colbase + j];
#pragma unroll
    for (int i2 = 0; i2 < 4; ++i2) {
        int m0 = bm + ty * 8 + 2 * i2;
        float* base0 = outp + (size_t)m0 * G4 + ((colbase & 255) << 2) + gate;
        float* base1 = base0 + G4;
#pragma unroll
        for (int j = 0; j < 8; ++j) {
            float2 p = unpack2(acc2[i2][j]);
            base0[j * 4] = p.x + bb8[j];
            base1[j * 4] = p.y + bb8[j];
        }
    }
}

// ============================================================================
__global__ void dummy_kernel(int v)
{
    g_dummy[threadIdx.x] = (float)v;
}

// ---------------- LSTM inner-loop body (function, NOT macro) ----------------
__device__ __forceinline__ void mma_k(
    ulonglong2 wv, float4 hA, float4 hB, ull* acc0, ull* acc1)
{
    ull hd0 = pack2(hA.x, hA.x), hd1 = pack2(hA.y, hA.y);
    ull hd2 = pack2(hA.z, hA.z), hd3 = pack2(hA.w, hA.w);
    ull hd4 = pack2(hB.x, hB.x), hd5 = pack2(hB.y, hB.y);
    ull hd6 = pack2(hB.z, hB.z), hd7 = pack2(hB.w, hB.w);
    acc0[0] = fma2(wv.x, hd0, acc0[0]); acc1[0] = fma2(wv.y, hd0, acc1[0]);
    acc0[1] = fma2(wv.x, hd1, acc0[1]); acc1[1] = fma2(wv.y, hd1, acc1[1]);
    acc0[2] = fma2(wv.x, hd2, acc0[2]); acc1[2] = fma2(wv.y, hd2, acc1[2]);
    acc0[3] = fma2(wv.x, hd3, acc0[3]); acc1[3] = fma2(wv.y, hd3, acc1[3]);
    acc0[4] = fma2(wv.x, hd4, acc0[4]); acc1[4] = fma2(wv.y, hd4, acc1[4]);
    acc0[5] = fma2(wv.x, hd5, acc0[5]); acc1[5] = fma2(wv.y, hd5, acc1[5]);
    acc0[6] = fma2(wv.x, hd6, acc0[6]); acc1[6] = fma2(wv.y, hd6, acc1[6]);
    acc0[7] = fma2(wv.x, hd7, acc0[7]); acc1[7] = fma2(wv.y, hd7, acc1[7]);
}

// ============================================================================
// Kernel 2: BiLSTM, 8-CTA clusters. Minimum-delivered-bytes mma:
// thread (mma role) = unit ct (4 gate-interleaved cols as natural ull2 pair,
// no duplication) x ALL 8 batches (natural 2x float4), k-slice of 32.
// 48 B LDS -> 32 MACs (1.5 B/MAC, was 3). h dup happens in registers (mov).
// Output role: thread = (u, b). rbuf padded [b][257 ull2], conflict-free.
// ============================================================================
__global__ void __cluster_dims__(8, 1, 1) __launch_bounds__(256, 1) lstm_kernel(
    const float* __restrict__ whhf, const float* __restrict__ whhb)
{
    extern __shared__ __align__(16) float sm[];
    float* ws   = sm;                 // [256 k][128 c] gate-interleaved 131072 B
    float* hs   = sm + 32768;         // [2][256 k][8 b] natural          16384 B
    float* rbuf = sm + 32768 + 4096;  // [8 b][257 ull2]                  32896 B

    int tid = threadIdx.x;
    int cid = blockIdx.x >> 3;
    int r   = blockIdx.x & 7;
    int dir = cid >> 3;
    int B0  = (cid & 7) * 8;
    const float* Whh = dir ? whhb : whhf;
    const float* xg  = dir ? g_xg_b : g_xg_f;
    float*       hh  = dir ? g_h_b  : g_h_f;

    // weights gate-interleaved: ws[k][u*4+g] = Whh[(g*256 + r*32 + u)*256 + k]
    for (int idx = tid; idx < 32768; idx += 256) {
        int c = idx >> 8, k = idx & 255;
        int u_ = c >> 2, g = c & 3;
        ws[k * 128 + c] = Whh[(size_t)(g * 256 + r * 32 + u_) * 256 + k];
    }
    for (int i = tid; i < 1024; i += 256)   // zero hs (both buffers)
        ((float4*)hs)[i] = make_float4(0.f, 0.f, 0.f, 0.f);
    __syncthreads();

    int ct = tid & 31, ks = tid >> 5;       // mma role: unit ct, k in [ks*32,+32)
    int u  = tid >> 3, b = tid & 7;         // output role
    float creg = 0.f;

    unsigned hsa = smem_u32(hs);
    unsigned rb[8];
#pragma unroll
    for (int j = 0; j < 8; ++j)
        rb[j] = mapa_u32(hsa, (unsigned)j) + (unsigned)(((r * 32 + u) * 8 + b) * 4);

    const ulonglong2* wq  = (const ulonglong2*)ws + ct;            // + k*32
    const float4*     hq  = (const float4*)hs;                     // + buf*512 + k*2
    ulonglong2*       rbw = (ulonglong2*)rbuf + (ks * 32 + ct);    // + bb*257
    const ulonglong2* rbr = (const ulonglong2*)rbuf + b * 257 + u; // + q*32
    int k0 = ks * 32;

    // prefetch xg (gate-interleaved float4 {i,f,g,o}) for it = 0
    int s0_ = dir ? 255 : 0;
    float4 xv = *(const float4*)&xg[((size_t)(s0_ * 64 + B0 + b)) * G4 + (r * 32 + u) * 4];

    for (int it = 0; it < 256; ++it) {
        int s = dir ? (255 - it) : it;
        int buf = it & 1, nbuf = buf ^ 1;

        ull acc0[8], acc1[8];
#pragma unroll
        for (int j = 0; j < 8; ++j) { acc0[j] = 0ULL; acc1[j] = 0ULL; }
        const float4* hqb = hq + buf * 512;

        // ---- mma: 8 chunks of 4 k; per k: 3x LDS.128 + 8 mov + 16 fma2 ----
#pragma unroll
        for (int c = 0; c < 8; ++c) {
            int kb = k0 + c * 4;
            ulonglong2 w0 = wq[(kb + 0) * 32];
            ulonglong2 w1 = wq[(kb + 1) * 32];
            ulonglong2 w2 = wq[(kb + 2) * 32];
            ulonglong2 w3 = wq[(kb + 3) * 32];
            float4 hA0 = hqb[(kb + 0) * 2], hB0 = hqb[(kb + 0) * 2 + 1];
            float4 hA1 = hqb[(kb + 1) * 2], hB1 = hqb[(kb + 1) * 2 + 1];
            float4 hA2 = hqb[(kb + 2) * 2], hB2 = hqb[(kb + 2) * 2 + 1];
            float4 hA3 = hqb[(kb + 3) * 2], hB3 = hqb[(kb + 3) * 2 + 1];
            mma_k(w0, hA0, hB0, acc0, acc1);
            mma_k(w1, hA1, hB1, acc0, acc1);
            mma_k(w2, hA2, hB2, acc0, acc1);
            mma_k(w3, hA3, hB3, acc0, acc1);
        }

        // ---- k-split partials to padded rbuf (conflict-free) ----
#pragma unroll
        for (int bb = 0; bb < 8; ++bb) {
            ulonglong2 v; v.x = acc0[bb]; v.y = acc1[bb];
            rbw[bb * 257] = v;
        }
        __syncthreads();

        // ---- reduce 8 partials for output (u, b) ----
        ull t0 = 0ULL, t1 = 0ULL;
#pragma unroll
        for (int q = 0; q < 8; ++q) {
            ulonglong2 v = rbr[q * 32];
            t0 = add2(t0, v.x);
            t1 = add2(t1, v.y);
        }
        float2 p0 = unpack2(t0), p1 = unpack2(t1);
        float iv = p0.x + xv.x, fv = p0.y + xv.y;
        float gv = p1.x + xv.z, ov = p1.y + xv.w;
        creg = fsigmoid(fv) * creg + fsigmoid(iv) * ftanh(gv);
        float hv = fsigmoid(ov) * ftanh(creg);

        if (it != 255) {
            // broadcast h to all 8 CTAs' hs[nbuf] (scalar; R11-measured equal)
            unsigned noff = (unsigned)(nbuf * 8192);
#pragma unroll
            for (int j = 0; j < 8; ++j) st_cluster_f32(rb[j] + noff, hv);
            CLUSTER_ARRIVE();

            hh[(size_t)s * 16384 + (r * 32 + u) * 64 + B0 + b] = hv;
            int sn = dir ? (s - 1) : (s + 1);
            xv = *(const float4*)&xg[((size_t)(sn * 64 + B0 + b)) * G4 + (r * 32 + u) * 4];
            CLUSTER_WAIT();
        } else {
            hh[(size_t)s * 16384 + (r * 32 + u) * 64 + B0 + b] = hv;
        }
    }
}

// ============================================================================
// Kernel 3: emissions (unchanged).
// ============================================================================
__global__ void __launch_bounds__(256) emis_kernel(
    const float* __restrict__ w_out, const float* __restrict__ b_out)
{
    extern __shared__ __align__(16) float hsm[];
    int s = blockIdx.x >> 1, half = blockIdx.x & 1;
    int tid = threadIdx.x;

    const float4* hf = (const float4*)(g_h_f + (size_t)s * 16384) + half * 8;
    const float4* hb = (const float4*)(g_h_b + (size_t)s * 16384) + half * 8;
    for (int f = tid; f < 2048; f += 256) {
        int u = f >> 3, q = f & 7;
        ((float4*)hsm)[u * 8 + q]        = hf[u * 16 + q];
        ((float4*)hsm)[2048 + u * 8 + q] = hb[u * 16 + q];
    }
    __syncthreads();

    for (int o = tid; o < TT * 32; o += 256) {
        int t = o >> 5, b = o & 31;
        const float4* wr = (const float4*)(w_out + (size_t)t * 512);
        float acc = 0.f;
#pragma unroll 4
        for (int u4 = 0; u4 < 128; ++u4) {
            float4 w = __ldg(wr + u4);
            acc += hsm[(u4 * 4 + 0) * 32 + b] * w.x
                 + hsm[(u4 * 4 + 1) * 32 + b] * w.y
                 + hsm[(u4 * 4 + 2) * 32 + b] * w.z
                 + hsm[(u4 * 4 + 3) * 32 + b] * w.w;
        }
        g_emit[((size_t)(half * 32 + b) * SQ + s) * TT + t] = acc + __ldg(b_out + t);
    }
}

// ============================================================================
// Kernel 4: CRF NLL (unchanged).
// ============================================================================
__global__ void __launch_bounds__(64) crf_kernel(
    const int* __restrict__ tags,
    const float* __restrict__ start_t, const float* __restrict__ end_t,
    const float* __restrict__ trans)
{
    __shared__ float bufA[40], bufB[40];
    __shared__ float red[64];
    int b = blockIdx.x, tid = threadIdx.x;
    const float* em = g_emit + (size_t)b * SQ * TT;

    float trw[TT];
    float emv_nxt = 0.f;
    if (tid < TT) {
#pragma unroll
        for (int t = 0; t < TT; ++t) trw[t] = __ldg(&trans[t * TT + tid]);
        bufA[tid] = start_t[tid] + em[tid];
        emv_nxt = em[TT + tid];
    }
    __syncthreads();

    float* cur = bufA;
    float* nxt = bufB;
    for (int s = 1; s < SQ; ++s) {
        if (tid < TT) {
            float emv = emv_nxt;
            if (s + 1 < SQ) emv_nxt = em[(s + 1) * TT + tid];
            float C = cur[0];
            float s0 = 0.f, s1 = 0.f, s2 = 0.f, s3 = 0.f;
#pragma unroll
            for (int i = 0; i < 8; ++i) {
                s0 += __expf(cur[4 * i + 0] + trw[4 * i + 0] - C);
                s1 += __expf(cur[4 * i + 1] + trw[4 * i + 1] - C);
                s2 += __expf(cur[4 * i + 2] + trw[4 * i + 2] - C);
                s3 += __expf(cur[4 * i + 3] + trw[4 * i + 3] - C);
            }
            s0 += __expf(cur[32] + trw[32] - C);
            s1 += __expf(cur[33] + trw[33] - C);
            nxt[tid] = C + __logf((s0 + s1) + (s2 + s3)) + emv;
        }
        __syncthreads();
        float* t_ = cur; cur = nxt; nxt = t_;
    }

    const int* tb = tags + b * SQ;
    float np = 0.f;
    for (int s = tid; s < SQ; s += 64)     np += em[s * TT + tb[s]];
    for (int s = tid; s < SQ - 1; s += 64) np += __ldg(&trans[tb[s] * TT + tb[s + 1]]);
    red[tid] = np;
    __syncthreads();
    if (tid < 32) {
        float a = red[tid] + red[tid + 32];
#pragma unroll
        for (int o = 16; o > 0; o >>= 1) a += __shfl_xor_sync(0xffffffffu, a, o);
        if (tid == 0) {
            float C = cur[0];
            float sum = 0.f;
            for (int q = 0; q < TT; ++q) sum += __expf(cur[q] + end_t[q] - C);
            float den = C + __logf(sum);
            float num = a + start_t[tb[0]] + end_t[tb[SQ - 1]];
            g_llh[b] = num - den;
        }
    }
}

// ============================================================================
__global__ void __launch_bounds__(64) finalize_kernel(float* out)
{
    __shared__ float r[64];
    int t = threadIdx.x;
    r[t] = g_llh[t];
    __syncthreads();
    for (int o = 32; o > 0; o >>= 1) {
        if (t < o) r[t] += r[t + o];
        __syncthreads();
    }
    if (t == 0) out[0] = -r[0] / 64.f;
}

// ============================================================================
extern "C" void kernel_launch(void* const* d_in, const int* in_sizes, int n_in,
                              void* d_out, int out_size)
{
    const int*   batch   = (const int*)  d_in[0];
    const int*   tags    = (const int*)  d_in[1];
    const float* emb     = (const float*)d_in[3];
    const float* w_ih_f  = (const float*)d_in[4];
    const float* w_hh_f  = (const float*)d_in[5];
    const float* b_f     = (const float*)d_in[6];
    const float* w_ih_b  = (const float*)d_in[7];
    const float* w_hh_b  = (const float*)d_in[8];
    const float* b_b     = (const float*)d_in[9];
    const float* w_out   = (const float*)d_in[10];
    const float* b_out   = (const float*)d_in[11];
    const float* start_t = (const float*)d_in[12];
    const float* end_t   = (const float*)d_in[13];
    const float* trans   = (const float*)d_in[14];
    float* out = (float*)d_out;

    const int LSTM_SMEM = 131072 + 16384 + 32896;   // 180352 B
    const int EMIS_SMEM = 512 * 32 * 4;             // 65536 B
    cudaFuncSetAttribute(lstm_kernel, cudaFuncAttributeMaxDynamicSharedMemorySize, LSTM_SMEM);
    cudaFuncSetAttribute(emis_kernel, cudaFuncAttributeMaxDynamicSharedMemorySize, EMIS_SMEM);

    input_gemm<<<dim3(16, 128), 256>>>(emb, batch, w_ih_f, b_f, w_ih_b, b_b);  // slot 1
    dummy_kernel<<<1, 32>>>(1);                                                // slot 2
    dummy_kernel<<<1, 32>>>(2);                                                // slot 3
    lstm_kernel<<<128, 256, LSTM_SMEM>>>(w_hh_f, w_hh_b);                      // slot 4 <- profiled
    emis_kernel<<<512, 256, EMIS_SMEM>>>(w_out, b_out);                        // slot 5
    crf_kernel<<<64, 64>>>(tags, start_t, end_t, trans);                       // slot 6
    finalize_kernel<<<1, 64>>>(out);                                           // slot 7
}